// round 16
// baseline (speedup 1.0000x reference)
#include <cuda_runtime.h>
#include <math.h>

#define NUx 128
#define MSx 64
#define INC 323      // inputs row stride: NU + MS + DT + 3
#define BMAX 4096
#define BN (BMAX * NUx)

typedef unsigned long long u64;

// ---------------- scratch (device globals: no allocation allowed) ----------
__device__ float g_base[BN];     // per-b part of gate3 pre-activation
__device__ float g_lg[BN];       // learning gain
__device__ float g_preds[BMAX];  // preds (already /128)
__device__ float g_ztop[BN];     // topic @ out_W[128:256] pre-activation part
__device__ float g_S[3 * NUx];   // column sums of gate3_W rows 256..405

__device__ __forceinline__ float sigf(float x) { return 1.f / (1.f + __expf(-x)); }
__device__ __forceinline__ float gainf(float f) {
    return 0.3f + 0.7f / (1.f + __expf(-10.f * (f - 0.3f)));
}

// ---- packed f32x2 helpers (sm_103a FFMA2) ----------------------------------
__device__ __forceinline__ u64 pk2(float lo, float hi) {
    u64 r; asm("mov.b64 %0, {%1, %2};" : "=l"(r) : "f"(lo), "f"(hi)); return r;
}
__device__ __forceinline__ float2 up2(u64 v) {
    float2 f; asm("mov.b64 {%0, %1}, %2;" : "=f"(f.x), "=f"(f.y) : "l"(v)); return f;
}
__device__ __forceinline__ u64 fma2(u64 a, u64 b, u64 c) {
    u64 d; asm("fma.rn.f32x2 %0, %1, %2, %3;" : "=l"(d) : "l"(a), "l"(b), "l"(c)); return d;
}

// batch-index swizzle for 32-wide transposed smem tiles
__device__ __forceinline__ int SWZ(int n, int i) {
    return n * 32 + (i ^ ((n & 3) << 3));
}

// ---------------- k0: fold the 3x50 broadcast rows of gate3_W --------------
__global__ void k0_sums(const float* __restrict__ g3W) {
    int n = threadIdx.x;  // 128 threads
    float s0 = 0.f, s1 = 0.f, s2 = 0.f;
#pragma unroll
    for (int u = 0; u < 50; u++) {
        s0 += g3W[(256 + u) * NUx + n];
        s1 += g3W[(306 + u) * NUx + n];
        s2 += g3W[(356 + u) * NUx + n];
    }
    g_S[n] = s0; g_S[NUx + n] = s1; g_S[2 * NUx + n] = s2;
}

// ---------------- k2: hpt prelude + gates + preds + base + ztop + fusion ---
// 32 batches per CTA, 512 threads.
// dyn smem floats: sAT 384*32 | sGT 3*128*32 | scorr 32*64 | sTAH 96 | sGain 96 | sPred 32
#define K2_SMEM_FLOATS (12288 + 12288 + 2048 + 96 + 96 + 32)

__global__ __launch_bounds__(512) void k2_gates(
    const float* __restrict__ inputs, const float* __restrict__ states,
    const float* __restrict__ tgW, const float* __restrict__ tgb,
    const float* __restrict__ agW, const float* __restrict__ agb,
    const float* __restrict__ hgW, const float* __restrict__ hgb,
    const float* __restrict__ outW, const float* __restrict__ outb,
    const float* __restrict__ g3W, const float* __restrict__ g3b,
    const float* __restrict__ tW, const float* __restrict__ aW,
    const float* __restrict__ hW,
    const float* __restrict__ Wf, const float* __restrict__ bias) {
    extern __shared__ float sm[];
    float* sAT   = sm;              // [384][32] swizzled: 0..127 hpt, 128..255 interact, 256..383 topic
    float* sGT   = sm + 12288;      // [3][128][32] swizzled
    float* scorr = sGT + 12288;     // [32][64]
    float* sTAH  = scorr + 2048;    // [32][3]
    float* sGain = sTAH + 96;       // [32][3]
    float* sPred = sGain + 96;      // [32]

    int tid = threadIdx.x;
    int b0 = blockIdx.x * 32;

    // ---- stage inputs-derived tiles ----
    for (int idx = tid; idx < 32 * 128; idx += 512) {
        int i = idx >> 7, n = idx & 127;
        size_t ib = (size_t)(b0 + i);
        sAT[SWZ(128 + n, i)] = inputs[ib * INC + n];          // interact
        sAT[SWZ(256 + n, i)] = inputs[ib * INC + 192 + n];    // topic
    }
    for (int idx = tid; idx < 32 * 64; idx += 512) {
        int i = idx >> 6, m = idx & 63;
        scorr[idx] = inputs[(size_t)(b0 + i) * INC + NUx + m];
    }
    if (tid < 32) {
        size_t ib = (size_t)(b0 + tid);
        float t = inputs[ib * INC + 320];
        float a = inputs[ib * INC + 321];
        float h = inputs[ib * INC + 322];
        sTAH[tid * 3 + 0] = t; sTAH[tid * 3 + 1] = a; sTAH[tid * 3 + 2] = h;
        sGain[tid * 3 + 0] = gainf(t);
        sGain[tid * 3 + 1] = gainf(a);
        sGain[tid * 3 + 2] = gainf(h);
        sPred[tid] = 0.f;
    }
    __syncthreads();

    // ---- prelude: h_pre_tilde directly into sAT rows 0..127 (was k1) ----
    {
        int nn = tid & 127, g4 = tid >> 7;  // g4 in 0..3
#pragma unroll 1
        for (int ii = 0; ii < 8; ii++) {
            int i = g4 * 8 + ii;
            const float* hp = states + (size_t)(b0 + i) * MSx * NUx + nn;
            const float* cm = scorr + i * 64;
            float acc = 0.f;
#pragma unroll 8
            for (int m = 0; m < 64; m++) acc += cm[m] * hp[(size_t)m * NUx];
            sAT[SWZ(nn, i)] = acc;
        }
    }
    __syncthreads();

    const int n2 = (tid & 63) << 1;   // two n-columns per thread
    const int i2 = tid >> 6;          // 0..7
    const int iB = i2 * 4;            // 4 batch rows per thread

    // ---- pass A1: three gate matvecs (float2 weights, f32x2 accs) ----
    u64 zt[2][2] = {{0,0},{0,0}}, za[2][2] = {{0,0},{0,0}}, zh[2][2] = {{0,0},{0,0}};
#pragma unroll 2
    for (int u = 0; u < 256; u++) {
        float2 wt = __ldg((const float2*)(tgW + u * NUx + n2));
        float2 wa = __ldg((const float2*)(agW + u * NUx + n2));
        float2 wh = __ldg((const float2*)(hgW + u * NUx + n2));
        ulonglong2 x = *(const ulonglong2*)(sAT + SWZ(u, iB));
        u64 wt0 = pk2(wt.x, wt.x), wt1 = pk2(wt.y, wt.y);
        u64 wa0 = pk2(wa.x, wa.x), wa1 = pk2(wa.y, wa.y);
        u64 wh0 = pk2(wh.x, wh.x), wh1 = pk2(wh.y, wh.y);
        zt[0][0] = fma2(x.x, wt0, zt[0][0]); zt[0][1] = fma2(x.y, wt0, zt[0][1]);
        zt[1][0] = fma2(x.x, wt1, zt[1][0]); zt[1][1] = fma2(x.y, wt1, zt[1][1]);
        za[0][0] = fma2(x.x, wa0, za[0][0]); za[0][1] = fma2(x.y, wa0, za[0][1]);
        za[1][0] = fma2(x.x, wa1, za[1][0]); za[1][1] = fma2(x.y, wa1, za[1][1]);
        zh[0][0] = fma2(x.x, wh0, zh[0][0]); zh[0][1] = fma2(x.y, wh0, zh[0][1]);
        zh[1][0] = fma2(x.x, wh1, zh[1][0]); zh[1][1] = fma2(x.y, wh1, zh[1][1]);
    }
    {
        float2 tb = __ldg((const float2*)(tgb + n2));
        float2 ab = __ldg((const float2*)(agb + n2));
        float2 hb = __ldg((const float2*)(hgb + n2));
#pragma unroll
        for (int p = 0; p < 2; p++) {
            int i0 = iB + 2 * p, i1 = i0 + 1;
            float2 t0 = up2(zt[0][p]), t1 = up2(zt[1][p]);
            float2 a0 = up2(za[0][p]), a1 = up2(za[1][p]);
            float2 h0 = up2(zh[0][p]), h1 = up2(zh[1][p]);
            float gT0 = sGain[i0*3+0], gT1 = sGain[i1*3+0];
            float gA0 = sGain[i0*3+1], gA1 = sGain[i1*3+1];
            float gH0 = sGain[i0*3+2], gH1 = sGain[i1*3+2];
            sGT[SWZ(n2,   i0)] = sigf((t0.x + tb.x) * gT0);
            sGT[SWZ(n2,   i1)] = sigf((t0.y + tb.x) * gT1);
            sGT[SWZ(n2+1, i0)] = sigf((t1.x + tb.y) * gT0);
            sGT[SWZ(n2+1, i1)] = sigf((t1.y + tb.y) * gT1);
            sGT[4096 + SWZ(n2,   i0)] = sigf((a0.x + ab.x) * gA0);
            sGT[4096 + SWZ(n2,   i1)] = sigf((a0.y + ab.x) * gA1);
            sGT[4096 + SWZ(n2+1, i0)] = sigf((a1.x + ab.y) * gA0);
            sGT[4096 + SWZ(n2+1, i1)] = sigf((a1.y + ab.y) * gA1);
            sGT[8192 + SWZ(n2,   i0)] = sigf((h0.x + hb.x) * gH0);
            sGT[8192 + SWZ(n2,   i1)] = sigf((h0.y + hb.x) * gH1);
            sGT[8192 + SWZ(n2+1, i0)] = sigf((h1.x + hb.y) * gH0);
            sGT[8192 + SWZ(n2+1, i1)] = sigf((h1.y + hb.y) * gH1);
        }
    }

    // ---- pass A2: preds (hpt part + topic part separately) + gate3 base ----
    u64 zph[2][2] = {{0,0},{0,0}}, zpt[2][2] = {{0,0},{0,0}}, zbb[2][2] = {{0,0},{0,0}};
#pragma unroll 2
    for (int u = 0; u < 128; u++) {
        float2 wp1 = __ldg((const float2*)(outW + u * NUx + n2));
        float2 wp2 = __ldg((const float2*)(outW + (128 + u) * NUx + n2));
        float2 wb  = __ldg((const float2*)(g3W + (128 + u) * NUx + n2));
        ulonglong2 xh = *(const ulonglong2*)(sAT + SWZ(u, iB));
        ulonglong2 xi = *(const ulonglong2*)(sAT + SWZ(128 + u, iB));
        ulonglong2 xt = *(const ulonglong2*)(sAT + SWZ(256 + u, iB));
        u64 w10 = pk2(wp1.x, wp1.x), w11 = pk2(wp1.y, wp1.y);
        u64 w20 = pk2(wp2.x, wp2.x), w21 = pk2(wp2.y, wp2.y);
        u64 wb0 = pk2(wb.x, wb.x),   wb1 = pk2(wb.y, wb.y);
        zph[0][0] = fma2(xh.x, w10, zph[0][0]); zph[0][1] = fma2(xh.y, w10, zph[0][1]);
        zph[1][0] = fma2(xh.x, w11, zph[1][0]); zph[1][1] = fma2(xh.y, w11, zph[1][1]);
        zpt[0][0] = fma2(xt.x, w20, zpt[0][0]); zpt[0][1] = fma2(xt.y, w20, zpt[0][1]);
        zpt[1][0] = fma2(xt.x, w21, zpt[1][0]); zpt[1][1] = fma2(xt.y, w21, zpt[1][1]);
        zbb[0][0] = fma2(xi.x, wb0, zbb[0][0]); zbb[0][1] = fma2(xi.y, wb0, zbb[0][1]);
        zbb[1][0] = fma2(xi.x, wb1, zbb[1][0]); zbb[1][1] = fma2(xi.y, wb1, zbb[1][1]);
    }
    {
        float2 ob = __ldg((const float2*)(outb + n2));
        float2 gb = __ldg((const float2*)(g3b + n2));
        float2 S0 = *(const float2*)(g_S + n2);
        float2 S1 = *(const float2*)(g_S + NUx + n2);
        float2 S2 = *(const float2*)(g_S + 2 * NUx + n2);
        float pj[4];
#pragma unroll
        for (int p = 0; p < 2; p++) {
            int i0 = iB + 2 * p, i1 = i0 + 1;
            float2 bh0 = up2(zbb[0][p]), bh1 = up2(zbb[1][p]);
            float2 ph0 = up2(zph[0][p]), ph1 = up2(zph[1][p]);
            float2 pt0 = up2(zpt[0][p]), pt1 = up2(zpt[1][p]);
            float t0 = sTAH[i0*3+0], a0 = sTAH[i0*3+1], h0 = sTAH[i0*3+2];
            float t1 = sTAH[i1*3+0], a1 = sTAH[i1*3+1], h1 = sTAH[i1*3+2];
            float2 v0 = make_float2(bh0.x + gb.x + t0*S0.x + a0*S1.x + h0*S2.x,
                                    bh1.x + gb.y + t0*S0.y + a0*S1.y + h0*S2.y);
            float2 v1 = make_float2(bh0.y + gb.x + t1*S0.x + a1*S1.x + h1*S2.x,
                                    bh1.y + gb.y + t1*S0.y + a1*S1.y + h1*S2.y);
            *(float2*)(g_base + (size_t)(b0 + i0) * NUx + n2) = v0;
            *(float2*)(g_base + (size_t)(b0 + i1) * NUx + n2) = v1;
            *(float2*)(g_ztop + (size_t)(b0 + i0) * NUx + n2) = make_float2(pt0.x, pt1.x);
            *(float2*)(g_ztop + (size_t)(b0 + i1) * NUx + n2) = make_float2(pt0.y, pt1.y);
            pj[2*p]   = sigf(ph0.x + pt0.x + ob.x) + sigf(ph1.x + pt1.x + ob.y);
            pj[2*p+1] = sigf(ph0.y + pt0.y + ob.x) + sigf(ph1.y + pt1.y + ob.y);
        }
#pragma unroll
        for (int j = 0; j < 4; j++) {
            float v = pj[j];
#pragma unroll
            for (int off = 16; off > 0; off >>= 1)
                v += __shfl_xor_sync(0xFFFFFFFFu, v, off);
            if ((tid & 31) == 0) atomicAdd(&sPred[iB + j], v);
        }
    }
    __syncthreads();
    if (tid < 32) g_preds[b0 + tid] = sPred[tid] * (1.f / 128.f);

    // ---- pass B: R=4 three-way fusion -> learning gain ----
    float lga[2][4] = {{0,0,0,0},{0,0,0,0}};
#pragma unroll 1
    for (int r = 0; r < 4; r++) {
        const float* tWr = tW + (size_t)r * 129 * NUx;
        const float* aWr = aW + (size_t)r * 129 * NUx;
        const float* hWr = hW + (size_t)r * 129 * NUx;
        u64 ft[2][2] = {{0,0},{0,0}}, fa[2][2] = {{0,0},{0,0}}, fh[2][2] = {{0,0},{0,0}};
#pragma unroll 2
        for (int u = 0; u < 128; u++) {
            float2 wt = __ldg((const float2*)(tWr + u * NUx + n2));
            float2 wa = __ldg((const float2*)(aWr + u * NUx + n2));
            float2 wh = __ldg((const float2*)(hWr + u * NUx + n2));
            ulonglong2 xt = *(const ulonglong2*)(sGT + SWZ(u, iB));
            ulonglong2 xa = *(const ulonglong2*)(sGT + 4096 + SWZ(u, iB));
            ulonglong2 xh = *(const ulonglong2*)(sGT + 8192 + SWZ(u, iB));
            u64 wt0 = pk2(wt.x, wt.x), wt1 = pk2(wt.y, wt.y);
            u64 wa0 = pk2(wa.x, wa.x), wa1 = pk2(wa.y, wa.y);
            u64 wh0 = pk2(wh.x, wh.x), wh1 = pk2(wh.y, wh.y);
            ft[0][0] = fma2(xt.x, wt0, ft[0][0]); ft[0][1] = fma2(xt.y, wt0, ft[0][1]);
            ft[1][0] = fma2(xt.x, wt1, ft[1][0]); ft[1][1] = fma2(xt.y, wt1, ft[1][1]);
            fa[0][0] = fma2(xa.x, wa0, fa[0][0]); fa[0][1] = fma2(xa.y, wa0, fa[0][1]);
            fa[1][0] = fma2(xa.x, wa1, fa[1][0]); fa[1][1] = fma2(xa.y, wa1, fa[1][1]);
            fh[0][0] = fma2(xh.x, wh0, fh[0][0]); fh[0][1] = fma2(xh.y, wh0, fh[0][1]);
            fh[1][0] = fma2(xh.x, wh1, fh[1][0]); fh[1][1] = fma2(xh.y, wh1, fh[1][1]);
        }
        float2 padT = __ldg((const float2*)(tWr + 128 * NUx + n2));
        float2 padA = __ldg((const float2*)(aWr + 128 * NUx + n2));
        float2 padH = __ldg((const float2*)(hWr + 128 * NUx + n2));
        float wfr   = __ldg(Wf + r);
#pragma unroll
        for (int p = 0; p < 2; p++) {
            float2 t0 = up2(ft[0][p]), t1 = up2(ft[1][p]);
            float2 a0 = up2(fa[0][p]), a1 = up2(fa[1][p]);
            float2 h0 = up2(fh[0][p]), h1 = up2(fh[1][p]);
            lga[0][2*p]   += wfr * (t0.x + padT.x) * (a0.x + padA.x) * (h0.x + padH.x);
            lga[0][2*p+1] += wfr * (t0.y + padT.x) * (a0.y + padA.x) * (h0.y + padH.x);
            lga[1][2*p]   += wfr * (t1.x + padT.y) * (a1.x + padA.y) * (h1.x + padH.y);
            lga[1][2*p+1] += wfr * (t1.y + padT.y) * (a1.y + padA.y) * (h1.y + padH.y);
        }
    }
    {
        float2 bn = __ldg((const float2*)(bias + n2));
#pragma unroll
        for (int j = 0; j < 4; j++) {
            float v0 = lga[0][j] + bn.x;
            float v1 = lga[1][j] + bn.y;
            *(float2*)(g_lg + (size_t)(b0 + iB + j) * NUx + n2) =
                make_float2(v0 > 0.f ? v0 : 0.f, v1 > 0.f ? v1 : 0.f);
        }
    }
}

// ---------------- k4: forget GEMM + h + h_tilde + after_preds (4 b/CTA) ----
// dyn smem: sW 16384 | sH 8192 | spart 2048 | shtl 128 | safter 256
#define K4_SMEM_FLOATS (16384 + 8192 + 2048 + 128 + 256)

__global__ __launch_bounds__(256) void k4_main(
    const float* __restrict__ inputs, const float* __restrict__ states,
    const float* __restrict__ g3W,
    const float* __restrict__ outW, const float* __restrict__ outb,
    float* __restrict__ out, float* __restrict__ out_h) {
    extern __shared__ float sm4[];
    float* sW     = sm4;            // [128][128]
    float* sH     = sm4 + 16384;    // [64][128] natural layout
    float* spart  = sH + 8192;      // [16][128]
    float* shtl   = spart + 2048;   // [128] htilde for current b
    float* safter = shtl + 128;     // [2][128]

    int tid = threadIdx.x;
    int bb = blockIdx.x * 4;

    // stage weights ONCE per CTA (4 batches)
    for (int idx = tid * 4; idx < 16384; idx += 1024)
        *(float4*)(sW + idx) = __ldg((const float4*)(g3W + idx));

    const int ty = tid >> 4, tx = tid & 15;
    const int m0 = ty * 4;
    const int na = tx * 4, nb = 64 + tx * 4;

#pragma unroll 1
    for (int ib = 0; ib < 4; ib++) {
        int b = bb + ib;
        __syncthreads();  // sH/spart/shtl free (covers W staging on ib=0)
        const float* hp = states + (size_t)b * MSx * NUx;
        for (int idx = tid * 4; idx < 8192; idx += 1024)
            *(float4*)(sH + idx) = *(const float4*)(hp + idx);
        __syncthreads();

        float4 bv0 = __ldg((const float4*)(g_base + (size_t)b * NUx + na));
        float4 bv1 = __ldg((const float4*)(g_base + (size_t)b * NUx + nb));
        u64 base2[4] = { pk2(bv0.x, bv0.y), pk2(bv0.z, bv0.w),
                         pk2(bv1.x, bv1.y), pk2(bv1.z, bv1.w) };
        u64 acc[4][4];
#pragma unroll
        for (int mi = 0; mi < 4; mi++)
#pragma unroll
            for (int p = 0; p < 4; p++) acc[mi][p] = base2[p];

#pragma unroll 2
        for (int k0 = 0; k0 < 128; k0 += 4) {
            float am[4][4];
#pragma unroll
            for (int mi = 0; mi < 4; mi++) {
                float4 a4 = *(const float4*)(sH + (m0 + mi) * NUx + k0);
                am[mi][0] = a4.x; am[mi][1] = a4.y; am[mi][2] = a4.z; am[mi][3] = a4.w;
            }
#pragma unroll
            for (int kk = 0; kk < 4; kk++) {
                const float* wr = sW + (k0 + kk) * NUx;
                ulonglong2 w0 = *(const ulonglong2*)(wr + na);
                ulonglong2 w1 = *(const ulonglong2*)(wr + nb);
                u64 wv[4] = {w0.x, w0.y, w1.x, w1.y};
#pragma unroll
                for (int mi = 0; mi < 4; mi++) {
                    u64 aa = pk2(am[mi][kk], am[mi][kk]);
#pragma unroll
                    for (int p = 0; p < 4; p++)
                        acc[mi][p] = fma2(aa, wv[p], acc[mi][p]);
                }
            }
        }

        // epilogue: fg = sigmoid(acc); h = h_pre*fg + corr[m]*lg[n]
        float cr[4];
#pragma unroll
        for (int mi = 0; mi < 4; mi++)
            cr[mi] = __ldg(inputs + (size_t)b * INC + NUx + m0 + mi);
        float4 lg0 = __ldg((const float4*)(g_lg + (size_t)b * NUx + na));
        float4 lg1 = __ldg((const float4*)(g_lg + (size_t)b * NUx + nb));
        float lgv[8] = {lg0.x, lg0.y, lg0.z, lg0.w, lg1.x, lg1.y, lg1.z, lg1.w};
        float pt[8] = {0,0,0,0,0,0,0,0};
        float* ob = out_h + (size_t)b * MSx * NUx;

#pragma unroll
        for (int mi = 0; mi < 4; mi++) {
            float4 ha  = *(const float4*)(sH + (m0 + mi) * NUx + na);
            float4 hb4 = *(const float4*)(sH + (m0 + mi) * NUx + nb);
            float hpv[8] = {ha.x, ha.y, ha.z, ha.w, hb4.x, hb4.y, hb4.z, hb4.w};
            float z[8];
#pragma unroll
            for (int p = 0; p < 4; p++) {
                float2 f = up2(acc[mi][p]);
                z[2*p] = f.x; z[2*p+1] = f.y;
            }
            float hv[8];
#pragma unroll
            for (int q = 0; q < 8; q++) {
                float fg = sigf(z[q]);
                hv[q] = hpv[q] * fg + cr[mi] * lgv[q];
                pt[q] += cr[mi] * hv[q];
            }
            *(float4*)(ob + (m0 + mi) * NUx + na) = make_float4(hv[0], hv[1], hv[2], hv[3]);
            *(float4*)(ob + (m0 + mi) * NUx + nb) = make_float4(hv[4], hv[5], hv[6], hv[7]);
        }
#pragma unroll
        for (int q = 0; q < 4; q++) {
            spart[ty * NUx + na + q] = pt[q];
            spart[ty * NUx + nb + q] = pt[4 + q];
        }
        __syncthreads();
        if (tid < 128) {
            float s = 0.f;
#pragma unroll
            for (int t = 0; t < 16; t++) s += spart[t * NUx + tid];
            shtl[tid] = s;   // htilde[b][tid]
        }
        __syncthreads();

        // after-preds: htilde @ outW[0:128] (+ ztop from k2) -> improve (was k5)
        {
            int n = tid & 127, half = tid >> 7;
            const float* hv = shtl + half * 64;
            const float* wp = outW + half * 64 * NUx + n;
            float accp = 0.f;
#pragma unroll 8
            for (int u = 0; u < 64; u++) accp += hv[u] * __ldg(wp + u * NUx);
            safter[half * NUx + n] = accp;
        }
        __syncthreads();
        if (tid < 128) {
            float z = safter[tid] + safter[NUx + tid] +
                      g_ztop[(size_t)b * NUx + tid] + __ldg(outb + tid);
            float pv = sigf(z);
#pragma unroll
            for (int off = 16; off > 0; off >>= 1)
                pv += __shfl_xor_sync(0xFFFFFFFFu, pv, off);
            if ((tid & 31) == 0) spart[tid >> 5] = pv;  // 4 warp sums
        }
        __syncthreads();
        if (tid == 0) {
            float after = (spart[0] + spart[1] + spart[2] + spart[3]) * (1.f / 128.f);
            float p = g_preds[b];
            out[2 * b]     = p;
            out[2 * b + 1] = (after - p) / (1.f - p);
        }
    }
}

// ---------------- launch ----------------------------------------------------
extern "C" void kernel_launch(void* const* d_in, const int* in_sizes, int n_in,
                              void* d_out, int out_size) {
    const float* inputs = (const float*)d_in[0];
    const float* states = (const float*)d_in[1];
    const float* tW     = (const float*)d_in[2];
    const float* aW     = (const float*)d_in[3];
    const float* hW     = (const float*)d_in[4];
    const float* Wf     = (const float*)d_in[5];
    const float* bias   = (const float*)d_in[6];
    const float* g3W    = (const float*)d_in[7];
    const float* g3b    = (const float*)d_in[8];
    const float* outW   = (const float*)d_in[9];
    const float* outb   = (const float*)d_in[10];
    const float* tgW    = (const float*)d_in[11];
    const float* tgb    = (const float*)d_in[12];
    const float* agW    = (const float*)d_in[13];
    const float* agb    = (const float*)d_in[14];
    const float* hgW    = (const float*)d_in[15];
    const float* hgb    = (const float*)d_in[16];

    int B = in_sizes[0] / INC;  // 4096
    float* out   = (float*)d_out;
    float* out_h = out + (size_t)2 * B;  // (result, h) flattened in tuple order

    const int smem2 = K2_SMEM_FLOATS * (int)sizeof(float);
    const int smem4 = K4_SMEM_FLOATS * (int)sizeof(float);
    cudaFuncSetAttribute(k2_gates, cudaFuncAttributeMaxDynamicSharedMemorySize, smem2);
    cudaFuncSetAttribute(k4_main, cudaFuncAttributeMaxDynamicSharedMemorySize, smem4);

    k0_sums<<<1, 128>>>(g3W);
    k2_gates<<<B / 32, 512, smem2>>>(inputs, states, tgW, tgb, agW, agb, hgW, hgb,
                                     outW, outb, g3W, g3b, tW, aW, hW, Wf, bias);
    k4_main<<<B / 4, 256, smem4>>>(inputs, states, g3W, outW, outb, out, out_h);
}

// round 17
// speedup vs baseline: 1.0823x; 1.0823x over previous
#include <cuda_runtime.h>
#include <math.h>

#define NUx 128
#define MSx 64
#define INC 323      // inputs row stride: NU + MS + DT + 3
#define BMAX 4096
#define BN (BMAX * NUx)

typedef unsigned long long u64;

// ---------------- scratch (device globals: no allocation allowed) ----------
__device__ float g_hpt[BN];      // h_pre_tilde
__device__ float g_base[BN];     // per-b part of gate3 pre-activation
__device__ float g_lg[BN];       // learning gain
__device__ float g_preds[BMAX];  // preds (already /128)
__device__ float g_htilde[BN];   // corr . h
__device__ float g_S[3 * NUx];   // column sums of gate3_W rows 256..405

__device__ __forceinline__ float sigf(float x) { return 1.f / (1.f + __expf(-x)); }
__device__ __forceinline__ float gainf(float f) {
    return 0.3f + 0.7f / (1.f + __expf(-10.f * (f - 0.3f)));
}

// ---- packed f32x2 helpers (sm_103a FFMA2) ----------------------------------
__device__ __forceinline__ u64 pk2(float lo, float hi) {
    u64 r; asm("mov.b64 %0, {%1, %2};" : "=l"(r) : "f"(lo), "f"(hi)); return r;
}
__device__ __forceinline__ float2 up2(u64 v) {
    float2 f; asm("mov.b64 {%0, %1}, %2;" : "=f"(f.x), "=f"(f.y) : "l"(v)); return f;
}
__device__ __forceinline__ u64 fma2(u64 a, u64 b, u64 c) {
    u64 d; asm("fma.rn.f32x2 %0, %1, %2, %3;" : "=l"(d) : "l"(a), "l"(b), "l"(c)); return d;
}

// ---------------- k0: fold the 3x50 broadcast rows of gate3_W --------------
__global__ void k0_sums(const float* __restrict__ g3W) {
    int n = threadIdx.x;  // 128 threads
    float s0 = 0.f, s1 = 0.f, s2 = 0.f;
#pragma unroll
    for (int u = 0; u < 50; u++) {
        s0 += g3W[(256 + u) * NUx + n];
        s1 += g3W[(306 + u) * NUx + n];
        s2 += g3W[(356 + u) * NUx + n];
    }
    g_S[n] = s0; g_S[NUx + n] = s1; g_S[2 * NUx + n] = s2;
}

// ---------------- k1: h_pre_tilde[b][n] = sum_m corr[m]*h_pre[m][n] --------
__global__ __launch_bounds__(256) void k1_hpt(const float* __restrict__ inputs,
                                              const float* __restrict__ states) {
    int b = blockIdx.x;
    int tid = threadIdx.x;
    int n = tid & 127, half = tid >> 7;  // half in {0,1}, m-range of 32
    __shared__ float sc[MSx];
    __shared__ float sp[2 * NUx];
    if (tid < MSx) sc[tid] = inputs[(size_t)b * INC + NUx + tid];
    __syncthreads();
    const float* hp = states + (size_t)b * MSx * NUx + (size_t)half * 32 * NUx;
    const float* cm = sc + half * 32;
    float acc = 0.f;
#pragma unroll 8
    for (int m = 0; m < 32; m++) acc += cm[m] * hp[(size_t)m * NUx + n];
    sp[half * NUx + n] = acc;
    __syncthreads();
    if (tid < NUx) g_hpt[(size_t)b * NUx + tid] = sp[tid] + sp[NUx + tid];
}

// ---------------- k2: gates + preds + base + fusion (16-batch, 512 thr) ----
// dyn smem floats: sAT 384*16 | sGT 3*128*16 | sTAH 48 | sGain 48 | sPred 16
// 16-batch tiles -> grid 256 -> 2 CTAs/SM co-residency (the occupancy fix)
#define K2_SMEM_FLOATS (6144 + 6144 + 48 + 48 + 16)

__global__ __launch_bounds__(512) void k2_gates(
    const float* __restrict__ inputs,
    const float* __restrict__ tgW, const float* __restrict__ tgb,
    const float* __restrict__ agW, const float* __restrict__ agb,
    const float* __restrict__ hgW, const float* __restrict__ hgb,
    const float* __restrict__ outW, const float* __restrict__ outb,
    const float* __restrict__ g3W, const float* __restrict__ g3b,
    const float* __restrict__ tW, const float* __restrict__ aW,
    const float* __restrict__ hW,
    const float* __restrict__ Wf, const float* __restrict__ bias) {
    extern __shared__ float sm[];
    float* sAT   = sm;             // [384][16]
    float* sGT   = sm + 6144;      // [3][128][16]
    float* sTAH  = sGT + 6144;     // [16][3]
    float* sGain = sTAH + 48;      // [16][3]
    float* sPred = sGain + 48;     // [16]

    int tid = threadIdx.x;
    int b0 = blockIdx.x * 16;

    for (int idx = tid; idx < 16 * 128; idx += 512) {
        int i = idx >> 7, n = idx & 127;
        size_t ib = (size_t)(b0 + i);
        sAT[n * 16 + i]         = g_hpt[ib * NUx + n];
        sAT[(128 + n) * 16 + i] = inputs[ib * INC + n];
        sAT[(256 + n) * 16 + i] = inputs[ib * INC + 192 + n];
    }
    if (tid < 16) {
        size_t ib = (size_t)(b0 + tid);
        float t = inputs[ib * INC + 320];
        float a = inputs[ib * INC + 321];
        float h = inputs[ib * INC + 322];
        sTAH[tid * 3 + 0] = t; sTAH[tid * 3 + 1] = a; sTAH[tid * 3 + 2] = h;
        sGain[tid * 3 + 0] = gainf(t);
        sGain[tid * 3 + 1] = gainf(a);
        sGain[tid * 3 + 2] = gainf(h);
        sPred[tid] = 0.f;
    }
    __syncthreads();

    const int i2 = tid >> 7;      // 0..3
    const int n  = tid & 127;
    const int iB = i2 * 4;        // 4 batch rows per thread

    // ---- pass A1: three gate matvecs (f32x2, 4 rows/thread) ----
    u64 zt[2] = {0,0}, za[2] = {0,0}, zh[2] = {0,0};
#pragma unroll 4
    for (int u = 0; u < 256; u++) {
        float wt = __ldg(tgW + u * NUx + n);
        float wa = __ldg(agW + u * NUx + n);
        float wh = __ldg(hgW + u * NUx + n);
        u64 wt2 = pk2(wt, wt), wa2 = pk2(wa, wa), wh2 = pk2(wh, wh);
        ulonglong2 x = *(const ulonglong2*)(sAT + u * 16 + iB);
        zt[0] = fma2(x.x, wt2, zt[0]); zt[1] = fma2(x.y, wt2, zt[1]);
        za[0] = fma2(x.x, wa2, za[0]); za[1] = fma2(x.y, wa2, za[1]);
        zh[0] = fma2(x.x, wh2, zh[0]); zh[1] = fma2(x.y, wh2, zh[1]);
    }
    {
        float tb = __ldg(tgb + n), ab = __ldg(agb + n), hb = __ldg(hgb + n);
#pragma unroll
        for (int p = 0; p < 2; p++) {
            float2 t = up2(zt[p]), a = up2(za[p]), h = up2(zh[p]);
            int i0 = iB + 2 * p, i1 = i0 + 1;
            sGT[n * 16 + i0]            = sigf((t.x + tb) * sGain[i0 * 3 + 0]);
            sGT[n * 16 + i1]            = sigf((t.y + tb) * sGain[i1 * 3 + 0]);
            sGT[2048 + n * 16 + i0]     = sigf((a.x + ab) * sGain[i0 * 3 + 1]);
            sGT[2048 + n * 16 + i1]     = sigf((a.y + ab) * sGain[i1 * 3 + 1]);
            sGT[2 * 2048 + n * 16 + i0] = sigf((h.x + hb) * sGain[i0 * 3 + 2]);
            sGT[2 * 2048 + n * 16 + i1] = sigf((h.y + hb) * sGain[i1 * 3 + 2]);
        }
    }

    // ---- pass A2: preds pre-activation + gate3 per-b base ----
    u64 zp[2] = {0,0}, zb[2] = {0,0};
#pragma unroll 4
    for (int u = 0; u < 128; u++) {
        float wp1 = __ldg(outW + u * NUx + n);
        float wp2 = __ldg(outW + (128 + u) * NUx + n);
        float wb  = __ldg(g3W + (128 + u) * NUx + n);
        u64 wp12 = pk2(wp1, wp1), wp22 = pk2(wp2, wp2), wb2 = pk2(wb, wb);
        ulonglong2 xh = *(const ulonglong2*)(sAT + u * 16 + iB);
        ulonglong2 xi = *(const ulonglong2*)(sAT + (128 + u) * 16 + iB);
        ulonglong2 xt = *(const ulonglong2*)(sAT + (256 + u) * 16 + iB);
        zp[0] = fma2(xh.x, wp12, zp[0]); zp[1] = fma2(xh.y, wp12, zp[1]);
        zp[0] = fma2(xt.x, wp22, zp[0]); zp[1] = fma2(xt.y, wp22, zp[1]);
        zb[0] = fma2(xi.x, wb2,  zb[0]); zb[1] = fma2(xi.y, wb2,  zb[1]);
    }
    {
        float ob = __ldg(outb + n), gb = __ldg(g3b + n);
        float S0 = g_S[n], S1 = g_S[NUx + n], S2 = g_S[2 * NUx + n];
        float pj[4];
#pragma unroll
        for (int p = 0; p < 2; p++) {
            float2 P = up2(zp[p]), Bv = up2(zb[p]);
            int i0 = iB + 2 * p, i1 = i0 + 1;
            size_t r0 = (size_t)(b0 + i0) * NUx + n;
            size_t r1 = (size_t)(b0 + i1) * NUx + n;
            g_base[r0] = Bv.x + gb + sTAH[i0*3+0]*S0 + sTAH[i0*3+1]*S1 + sTAH[i0*3+2]*S2;
            g_base[r1] = Bv.y + gb + sTAH[i1*3+0]*S0 + sTAH[i1*3+1]*S1 + sTAH[i1*3+2]*S2;
            pj[2*p]   = sigf(P.x + ob);
            pj[2*p+1] = sigf(P.y + ob);
        }
        // warp-level reduce over the 32 n's in this warp, then 1 atomic/warp/j
#pragma unroll
        for (int j = 0; j < 4; j++) {
            float v = pj[j];
#pragma unroll
            for (int off = 16; off > 0; off >>= 1)
                v += __shfl_xor_sync(0xFFFFFFFFu, v, off);
            if ((tid & 31) == 0) atomicAdd(&sPred[iB + j], v);
        }
    }
    __syncthreads();
    if (tid < 16) g_preds[b0 + tid] = sPred[tid] * (1.f / 128.f);

    // ---- pass B: R=4 three-way fusion -> learning gain ----
    float lga[4] = {0,0,0,0};
#pragma unroll 1
    for (int r = 0; r < 4; r++) {
        const float* tWr = tW + (size_t)r * 129 * NUx;
        const float* aWr = aW + (size_t)r * 129 * NUx;
        const float* hWr = hW + (size_t)r * 129 * NUx;
        u64 ft[2] = {0,0}, fa[2] = {0,0}, fh[2] = {0,0};
#pragma unroll 4
        for (int u = 0; u < 128; u++) {
            float wt = __ldg(tWr + u * NUx + n);
            float wa = __ldg(aWr + u * NUx + n);
            float wh = __ldg(hWr + u * NUx + n);
            u64 wt2 = pk2(wt, wt), wa2 = pk2(wa, wa), wh2 = pk2(wh, wh);
            ulonglong2 xt = *(const ulonglong2*)(sGT + u * 16 + iB);
            ulonglong2 xa = *(const ulonglong2*)(sGT + 2048 + u * 16 + iB);
            ulonglong2 xh = *(const ulonglong2*)(sGT + 2 * 2048 + u * 16 + iB);
            ft[0] = fma2(xt.x, wt2, ft[0]); ft[1] = fma2(xt.y, wt2, ft[1]);
            fa[0] = fma2(xa.x, wa2, fa[0]); fa[1] = fma2(xa.y, wa2, fa[1]);
            fh[0] = fma2(xh.x, wh2, fh[0]); fh[1] = fma2(xh.y, wh2, fh[1]);
        }
        float padT = __ldg(tWr + 128 * NUx + n);
        float padA = __ldg(aWr + 128 * NUx + n);
        float padH = __ldg(hWr + 128 * NUx + n);
        float wfr  = __ldg(Wf + r);
#pragma unroll
        for (int p = 0; p < 2; p++) {
            float2 t = up2(ft[p]), a = up2(fa[p]), h = up2(fh[p]);
            lga[2*p]   += wfr * (t.x + padT) * (a.x + padA) * (h.x + padH);
            lga[2*p+1] += wfr * (t.y + padT) * (a.y + padA) * (h.y + padH);
        }
    }
    {
        float bn = __ldg(bias + n);
#pragma unroll
        for (int j = 0; j < 4; j++) {
            float v = lga[j] + bn;
            g_lg[(size_t)(b0 + iB + j) * NUx + n] = v > 0.f ? v : 0.f;
        }
    }
}

// ---------------- k4: forget gate GEMM + h + h_tilde (2 b per CTA) ---------
// dyn smem: sW 128*128 | sH 64*128 natural | spart 16*128 | misc (2 b's)
#define K4_SMEM_FLOATS (16384 + 8192 + 2048 + 128 + 256 + 256)

__global__ __launch_bounds__(256) void k4_main(
    const float* __restrict__ inputs, const float* __restrict__ states,
    const float* __restrict__ g3W, float* __restrict__ out_h) {
    extern __shared__ float sm4[];
    float* sW    = sm4;            // [128][128]
    float* sH    = sm4 + 16384;    // [64][128]  natural layout
    float* spart = sH + 8192;      // [16][128]
    float* scorr = spart + 2048;   // [2][64]
    float* slg   = scorr + 128;    // [2][128]
    float* sbase = slg + 256;      // [2][128]

    int tid = threadIdx.x;
    int bb = blockIdx.x * 2;

    // stage weights ONCE per CTA
    for (int idx = tid * 4; idx < 16384; idx += 1024)
        *(float4*)(sW + idx) = __ldg((const float4*)(g3W + idx));
    // per-b vectors for both b's
    if (tid < 128) {
        int ib = tid >> 6, mm = tid & 63;
        scorr[tid] = inputs[(size_t)(bb + ib) * INC + NUx + mm];
    }
    {
        int ib = tid >> 7, n = tid & 127;
        slg[tid]   = g_lg[(size_t)(bb + ib) * NUx + n];
        sbase[tid] = g_base[(size_t)(bb + ib) * NUx + n];
    }

    const int ty = tid >> 4, tx = tid & 15;
    const int m0 = ty * 4;
    const int na = tx * 4, nb = 64 + tx * 4;

    for (int ib = 0; ib < 2; ib++) {
        int b = bb + ib;
        __syncthreads();  // sH/spart free (covers initial staging on ib=0)
        const float* hp = states + (size_t)b * MSx * NUx;
        for (int idx = tid * 4; idx < 8192; idx += 1024)
            *(float4*)(sH + idx) = *(const float4*)(hp + idx);
        __syncthreads();

        u64 base2[4] = { pk2(sbase[ib*128+na],   sbase[ib*128+na+1]),
                         pk2(sbase[ib*128+na+2], sbase[ib*128+na+3]),
                         pk2(sbase[ib*128+nb],   sbase[ib*128+nb+1]),
                         pk2(sbase[ib*128+nb+2], sbase[ib*128+nb+3]) };
        u64 acc[4][4];
#pragma unroll
        for (int mi = 0; mi < 4; mi++)
#pragma unroll
            for (int p = 0; p < 4; p++) acc[mi][p] = base2[p];

#pragma unroll 2
        for (int k0 = 0; k0 < 128; k0 += 4) {
            float am[4][4];
#pragma unroll
            for (int mi = 0; mi < 4; mi++) {
                float4 a4 = *(const float4*)(sH + (m0 + mi) * NUx + k0);
                am[mi][0] = a4.x; am[mi][1] = a4.y; am[mi][2] = a4.z; am[mi][3] = a4.w;
            }
#pragma unroll
            for (int kk = 0; kk < 4; kk++) {
                const float* wr = sW + (k0 + kk) * NUx;
                ulonglong2 w0 = *(const ulonglong2*)(wr + na);
                ulonglong2 w1 = *(const ulonglong2*)(wr + nb);
                u64 wv[4] = {w0.x, w0.y, w1.x, w1.y};
#pragma unroll
                for (int mi = 0; mi < 4; mi++) {
                    u64 aa = pk2(am[mi][kk], am[mi][kk]);
#pragma unroll
                    for (int p = 0; p < 4; p++)
                        acc[mi][p] = fma2(aa, wv[p], acc[mi][p]);
                }
            }
        }

        // epilogue: fg = sigmoid(acc); h = h_pre*fg + corr[m]*lg[n]
        float cr[4] = {scorr[ib*64+m0], scorr[ib*64+m0+1],
                       scorr[ib*64+m0+2], scorr[ib*64+m0+3]};
        float lgv[8] = {slg[ib*128+na], slg[ib*128+na+1], slg[ib*128+na+2], slg[ib*128+na+3],
                        slg[ib*128+nb], slg[ib*128+nb+1], slg[ib*128+nb+2], slg[ib*128+nb+3]};
        float pt[8] = {0,0,0,0,0,0,0,0};
        float* ob = out_h + (size_t)b * MSx * NUx;

#pragma unroll
        for (int mi = 0; mi < 4; mi++) {
            float4 ha  = *(const float4*)(sH + (m0 + mi) * NUx + na);
            float4 hb4 = *(const float4*)(sH + (m0 + mi) * NUx + nb);
            float hpv[8] = {ha.x, ha.y, ha.z, ha.w, hb4.x, hb4.y, hb4.z, hb4.w};
            float z[8];
#pragma unroll
            for (int p = 0; p < 4; p++) {
                float2 f = up2(acc[mi][p]);
                z[2*p] = f.x; z[2*p+1] = f.y;
            }
            float hv[8];
#pragma unroll
            for (int q = 0; q < 8; q++) {
                float fg = sigf(z[q]);
                hv[q] = hpv[q] * fg + cr[mi] * lgv[q];
                pt[q] += cr[mi] * hv[q];
            }
            *(float4*)(ob + (m0 + mi) * NUx + na) = make_float4(hv[0], hv[1], hv[2], hv[3]);
            *(float4*)(ob + (m0 + mi) * NUx + nb) = make_float4(hv[4], hv[5], hv[6], hv[7]);
        }
#pragma unroll
        for (int q = 0; q < 4; q++) {
            spart[ty * NUx + na + q] = pt[q];
            spart[ty * NUx + nb + q] = pt[4 + q];
        }
        __syncthreads();
        if (tid < 128) {
            float s = 0.f;
#pragma unroll
            for (int t = 0; t < 16; t++) s += spart[t * NUx + tid];
            g_htilde[(size_t)b * NUx + tid] = s;
        }
    }
}

// ---------------- k5: after_preds + improve -> result ----------------------
__global__ __launch_bounds__(512) void k5_result(
    const float* __restrict__ inputs, const float* __restrict__ outW,
    const float* __restrict__ outb, float* __restrict__ out) {
    __shared__ __align__(16) float sA[256 * 16];  // rows 0..127 htilde, 128..255 topic
    __shared__ float sAfter[16];
    int tid = threadIdx.x;
    int b0 = blockIdx.x * 16;
    for (int idx = tid; idx < 16 * 128; idx += 512) {
        int i = idx >> 7, n = idx & 127;
        size_t ib = (size_t)(b0 + i);
        sA[n * 16 + i]         = g_htilde[ib * NUx + n];
        sA[(128 + n) * 16 + i] = inputs[ib * INC + 192 + n];
    }
    if (tid < 16) sAfter[tid] = 0.f;
    __syncthreads();

    const int i2 = tid >> 7, n = tid & 127, iB = i2 * 4;
    u64 zp[2] = {0,0};
#pragma unroll 4
    for (int u = 0; u < 256; u++) {
        float w = __ldg(outW + u * NUx + n);
        u64 w2 = pk2(w, w);
        ulonglong2 x = *(const ulonglong2*)(sA + u * 16 + iB);
        zp[0] = fma2(x.x, w2, zp[0]);
        zp[1] = fma2(x.y, w2, zp[1]);
    }
    float ob = __ldg(outb + n);
    float pj[4];
    {
        float2 P0 = up2(zp[0]), P1 = up2(zp[1]);
        pj[0] = sigf(P0.x + ob); pj[1] = sigf(P0.y + ob);
        pj[2] = sigf(P1.x + ob); pj[3] = sigf(P1.y + ob);
    }
#pragma unroll
    for (int j = 0; j < 4; j++) {
        float v = pj[j];
#pragma unroll
        for (int off = 16; off > 0; off >>= 1)
            v += __shfl_xor_sync(0xFFFFFFFFu, v, off);
        if ((tid & 31) == 0) atomicAdd(&sAfter[iB + j], v);
    }
    __syncthreads();
    if (tid < 16) {
        int b = b0 + tid;
        float after = sAfter[tid] * (1.f / 128.f);
        float p = g_preds[b];
        out[2 * b]     = p;
        out[2 * b + 1] = (after - p) / (1.f - p);
    }
}

// ---------------- launch ----------------------------------------------------
extern "C" void kernel_launch(void* const* d_in, const int* in_sizes, int n_in,
                              void* d_out, int out_size) {
    const float* inputs = (const float*)d_in[0];
    const float* states = (const float*)d_in[1];
    const float* tW     = (const float*)d_in[2];
    const float* aW     = (const float*)d_in[3];
    const float* hW     = (const float*)d_in[4];
    const float* Wf     = (const float*)d_in[5];
    const float* bias   = (const float*)d_in[6];
    const float* g3W    = (const float*)d_in[7];
    const float* g3b    = (const float*)d_in[8];
    const float* outW   = (const float*)d_in[9];
    const float* outb   = (const float*)d_in[10];
    const float* tgW    = (const float*)d_in[11];
    const float* tgb    = (const float*)d_in[12];
    const float* agW    = (const float*)d_in[13];
    const float* agb    = (const float*)d_in[14];
    const float* hgW    = (const float*)d_in[15];
    const float* hgb    = (const float*)d_in[16];

    int B = in_sizes[0] / INC;  // 4096
    float* out   = (float*)d_out;
    float* out_h = out + (size_t)2 * B;  // (result, h) flattened in tuple order

    const int smem2 = K2_SMEM_FLOATS * (int)sizeof(float);
    const int smem4 = K4_SMEM_FLOATS * (int)sizeof(float);
    cudaFuncSetAttribute(k2_gates, cudaFuncAttributeMaxDynamicSharedMemorySize, smem2);
    cudaFuncSetAttribute(k4_main, cudaFuncAttributeMaxDynamicSharedMemorySize, smem4);

    k0_sums<<<1, 128>>>(g3W);
    k1_hpt<<<B, 256>>>(inputs, states);
    k2_gates<<<B / 16, 512, smem2>>>(inputs, tgW, tgb, agW, agb, hgW, hgb,
                                     outW, outb, g3W, g3b, tW, aW, hW, Wf, bias);
    k4_main<<<B / 2, 256, smem4>>>(inputs, states, g3W, out_h);
    k5_result<<<B / 16, 512>>>(inputs, outW, outb, out);
}